// round 11
// baseline (speedup 1.0000x reference)
#include <cuda_runtime.h>
#include <cuda_bf16.h>
#include <math.h>

// Problem dims (fixed by the dataset)
#define NSMP 256
#define NT   512
#define NX   512

// ---------------------------------------------------------------------------
// Device scratch (no cudaMalloc allowed)
// ---------------------------------------------------------------------------
__device__ int   g_T0[NSMP];
__device__ float g_LU[NX * NX];
__device__ float g_logabsdet;

// ---------------------------------------------------------------------------
// Kernel 1: per-sample shift T0[i] = min(argmin_t |phi[i,t,0]|, argmin_t |phi[i,t,1]|)
// jnp.argmin returns FIRST index of the minimum -> tie-break toward lower t.
// ---------------------------------------------------------------------------
__global__ void k_T0(const float* __restrict__ phi) {
    int i = blockIdx.x;
    int lane = threadIdx.x & 31;
    int x = threadIdx.x >> 5;  // 0 or 1
    const float* p = phi + (size_t)i * NT * NX + x;

    float best = 3.4e38f;
    int bidx = 0;
    for (int t = lane; t < NT; t += 32) {
        float v = fabsf(p[(size_t)t * NX]);
        if (v < best) { best = v; bidx = t; }  // ascending t per lane -> first min kept
    }
    #pragma unroll
    for (int off = 16; off > 0; off >>= 1) {
        float ov = __shfl_down_sync(0xffffffffu, best, off);
        int   oi = __shfl_down_sync(0xffffffffu, bidx, off);
        if (ov < best || (ov == best && oi < bidx)) { best = ov; bidx = oi; }
    }
    __shared__ int s[2];
    if (lane == 0) s[x] = bidx;
    __syncthreads();
    if (threadIdx.x == 0) g_T0[i] = min(s[0], s[1]);
}

// ---------------------------------------------------------------------------
// Kernel 2: copy W -> LU scratch, zero the logdet accumulator
// ---------------------------------------------------------------------------
__global__ void k_copyW(const float* __restrict__ W) {
    int idx = blockIdx.x * blockDim.x + threadIdx.x;  // 65536 float4s
    if (idx == 0) g_logabsdet = 0.0f;
    reinterpret_cast<float4*>(g_LU)[idx] = reinterpret_cast<const float4*>(W)[idx];
}

// ---------------------------------------------------------------------------
// Kernel 3: LU panel factorization (unpivoted), nb = 32, one block.
// Row-per-thread in registers, fully unrolled (no dynamic local indexing).
// Fused: U12 triangular solve for the trailing columns of this panel.
// Accumulates sum(log|u_jj|) into g_logabsdet. Panels run serially on one
// stream, so the float accumulation order is fixed -> deterministic.
// ---------------------------------------------------------------------------
__global__ void __launch_bounds__(512) k_lu_panel(int p) {
    const int col0 = p * 32;
    const int R = NX - col0;          // rows col0..511 participate
    const int t = threadIdx.x;        // 512 threads
    const bool act = (t < R);

    __shared__ float srow[32];
    __shared__ float s_rinv;
    __shared__ float sL[32][33];

    float a[32];
    float* rowp = g_LU + (size_t)(col0 + t) * NX + col0;
    if (act) {
        #pragma unroll
        for (int q = 0; q < 8; q++) {
            float4 v = *reinterpret_cast<const float4*>(rowp + 4 * q);
            a[4 * q + 0] = v.x; a[4 * q + 1] = v.y;
            a[4 * q + 2] = v.z; a[4 * q + 3] = v.w;
        }
    }

    float lsum = 0.0f;
    #pragma unroll
    for (int j = 0; j < 32; j++) {
        if (t == j) {
            #pragma unroll
            for (int k = 0; k < 32; k++) srow[k] = a[k];
            s_rinv = 1.0f / a[j];
        }
        __syncthreads();
        if (t == 0) lsum += logf(fabsf(srow[j]));
        if (act && t > j) {
            float l = a[j] * s_rinv;
            a[j] = l;
            #pragma unroll
            for (int k = j + 1; k < 32; k++) a[k] -= l * srow[k];
        }
        __syncthreads();  // protect srow for next step's writer
    }

    // write panel back
    if (act) {
        #pragma unroll
        for (int q = 0; q < 8; q++) {
            float4 v;
            v.x = a[4 * q + 0]; v.y = a[4 * q + 1];
            v.z = a[4 * q + 2]; v.w = a[4 * q + 3];
            *reinterpret_cast<float4*>(rowp + 4 * q) = v;
        }
    }
    if (t < 32) {
        #pragma unroll
        for (int k = 0; k < 32; k++) sL[t][k] = a[k];  // rows 0..31 hold L11 (k<t) / U11 (k>=t)
    }
    if (t == 0) atomicAdd(&g_logabsdet, lsum);
    __syncthreads();

    // U12 solve: columns col0+32 .. 511 ; y = L11^{-1} A12[:, c]
    const int nc = R - 32;
    if (t < nc) {
        const int c = col0 + 32 + t;
        float y[32];
        #pragma unroll
        for (int j = 0; j < 32; j++) y[j] = g_LU[(size_t)(col0 + j) * NX + c];
        #pragma unroll
        for (int k = 0; k < 32; k++) {
            #pragma unroll
            for (int j = k + 1; j < 32; j++) y[j] -= sL[j][k] * y[k];
        }
        #pragma unroll
        for (int j = 0; j < 32; j++) g_LU[(size_t)(col0 + j) * NX + c] = y[j];
    }
}

// ---------------------------------------------------------------------------
// Kernel 4: trailing Schur update  A22 -= L21 * U12  (K = 32)
// ---------------------------------------------------------------------------
__global__ void __launch_bounds__(1024) k_lu_trail(int p) {
    const int col0 = p * 32;
    const int r0 = col0 + 32 + blockIdx.y * 32;
    const int c0 = col0 + 32 + blockIdx.x * 32;
    const int ty = threadIdx.y, tx = threadIdx.x;

    __shared__ float sL[32][33];
    __shared__ float sU[32][33];
    sL[ty][tx] = g_LU[(size_t)(r0 + ty) * NX + col0 + tx];
    sU[ty][tx] = g_LU[(size_t)(col0 + ty) * NX + c0 + tx];
    __syncthreads();

    float acc = 0.0f;
    #pragma unroll
    for (int k = 0; k < 32; k++) acc += sL[ty][k] * sU[k][tx];
    g_LU[(size_t)(r0 + ty) * NX + c0 + tx] -= acc;
}

// ---------------------------------------------------------------------------
// Kernel 5: broadcast logDet
// ---------------------------------------------------------------------------
__global__ void k_logdet(float* __restrict__ dst) {
    int i = blockIdx.x * blockDim.x + threadIdx.x;
    if (i < NSMP) dst[i] = (float)NT * g_logabsdet;
}

// ---------------------------------------------------------------------------
// Kernel 6: fused double-roll batched SGEMM.
//   out[i, (t - T0)%NT, y] = sum_u phi[i,t,u] * W[(u + T0)%NX, y]
// 128x128 tile, BK=8, 256 threads, 8x8 micro-tile per thread.
// Register prefetch + DOUBLE-BUFFERED smem: one __syncthreads per K-iter.
// W row address kept as a running pointer (wrap-by-subtract, no per-iter mod).
// ---------------------------------------------------------------------------
#define BM 128
#define BN 128
#define BK 8

__global__ void __launch_bounds__(256) k_gemm(const float* __restrict__ phi,
                                              const float* __restrict__ W,
                                              float* __restrict__ out) {
    const int i = blockIdx.z;
    const int T0 = g_T0[i];
    const int m0 = blockIdx.y * BM;
    const int n0 = blockIdx.x * BN;
    const float* A = phi + (size_t)i * NT * NX;
    float* C = out + (size_t)i * NT * NX;

    __shared__ float As[2][BK][BM + 8];
    __shared__ float Bs[2][BK][BN];

    const int tid = threadIdx.x;
    const int tx = tid & 15;    // 0..15 -> output cols tx*8
    const int ty = tid >> 4;    // 0..15 -> output rows ty*8

    const int am = tid >> 1;          // 0..127
    const int ak = (tid & 1) * 4;     // 0 or 4
    const int bk = tid >> 5;          // 0..7
    const int bn = (tid & 31) * 4;

    const float* Aptr = A + (size_t)(m0 + am) * NX + ak;

    float acc[8][8];
    #pragma unroll
    for (int r = 0; r < 8; r++)
        #pragma unroll
        for (int c = 0; c < 8; c++) acc[r][c] = 0.0f;

    // running W pointer for this thread's row: row (T0 + bk + k0), wrap at NX
    int wk = bk + T0;                         // < NX + 8
    const float* Wp = W + (size_t)(wk & (NX - 1)) * NX + n0 + bn;
    if (wk >= NX) wk -= NX;                   // keep wk in [0, NX)

    // prologue: fetch tile 0, stage into buffer 0
    {
        float4 av = *reinterpret_cast<const float4*>(Aptr);
        float4 bv = *reinterpret_cast<const float4*>(Wp);
        As[0][ak + 0][am] = av.x; As[0][ak + 1][am] = av.y;
        As[0][ak + 2][am] = av.z; As[0][ak + 3][am] = av.w;
        *reinterpret_cast<float4*>(&Bs[0][bk][bn]) = bv;
    }
    __syncthreads();

    int buf = 0;
    for (int k0 = 0; k0 < NX; k0 += BK) {
        // prefetch next tile into registers (overlaps with FFMA block below)
        float4 av, bv;
        const bool more = (k0 + BK < NX);
        if (more) {
            wk += BK;
            Wp += (size_t)BK * NX;
            if (wk >= NX) { wk -= NX; Wp -= (size_t)NX * NX; }
            av = *reinterpret_cast<const float4*>(Aptr + k0 + BK);
            bv = *reinterpret_cast<const float4*>(Wp);
        }

        // compute from current buffer
        #pragma unroll
        for (int kk = 0; kk < BK; kk++) {
            float ar[8], br[8];
            float4 a0 = *reinterpret_cast<const float4*>(&As[buf][kk][ty * 8]);
            float4 a1 = *reinterpret_cast<const float4*>(&As[buf][kk][ty * 8 + 4]);
            ar[0] = a0.x; ar[1] = a0.y; ar[2] = a0.z; ar[3] = a0.w;
            ar[4] = a1.x; ar[5] = a1.y; ar[6] = a1.z; ar[7] = a1.w;
            float4 b0 = *reinterpret_cast<const float4*>(&Bs[buf][kk][tx * 8]);
            float4 b1 = *reinterpret_cast<const float4*>(&Bs[buf][kk][tx * 8 + 4]);
            br[0] = b0.x; br[1] = b0.y; br[2] = b0.z; br[3] = b0.w;
            br[4] = b1.x; br[5] = b1.y; br[6] = b1.z; br[7] = b1.w;
            #pragma unroll
            for (int r = 0; r < 8; r++)
                #pragma unroll
                for (int c = 0; c < 8; c++) acc[r][c] += ar[r] * br[c];
        }

        // stage prefetched tile into the other buffer
        if (more) {
            const int nb = buf ^ 1;
            As[nb][ak + 0][am] = av.x; As[nb][ak + 1][am] = av.y;
            As[nb][ak + 2][am] = av.z; As[nb][ak + 3][am] = av.w;
            *reinterpret_cast<float4*>(&Bs[nb][bk][bn]) = bv;
            __syncthreads();
            buf = nb;
        }
    }

    // write with row roll: output row = (t - T0) mod NT
    #pragma unroll
    for (int r = 0; r < 8; r++) {
        const int trow = m0 + ty * 8 + r;
        const int orow = (trow - T0) & (NT - 1);
        float* dst = C + (size_t)orow * NX + n0 + tx * 8;
        float4 v0, v1;
        v0.x = acc[r][0]; v0.y = acc[r][1]; v0.z = acc[r][2]; v0.w = acc[r][3];
        v1.x = acc[r][4]; v1.y = acc[r][5]; v1.z = acc[r][6]; v1.w = acc[r][7];
        *reinterpret_cast<float4*>(dst) = v0;
        *reinterpret_cast<float4*>(dst + 4) = v1;
    }
}

// ---------------------------------------------------------------------------
// Launch
// ---------------------------------------------------------------------------
extern "C" void kernel_launch(void* const* d_in, const int* in_sizes, int n_in,
                              void* d_out, int out_size) {
    const float* phi = (const float*)d_in[0];
    const float* W   = (const float*)d_in[1];
    if (n_in >= 2 && in_sizes[0] < in_sizes[1]) {  // guard against input-order surprises
        phi = (const float*)d_in[1];
        W   = (const float*)d_in[0];
    }
    float* out = (float*)d_out;
    // logDet slab: last NSMP elements of the flat output (layout: [out | logDet])
    float* logdet_out = out + (size_t)(out_size - NSMP);

    // T0 shifts
    k_T0<<<NSMP, 64>>>(phi);

    // logdet branch: copy W, blocked LU, broadcast
    k_copyW<<<256, 256>>>(W);
    for (int p = 0; p < 16; p++) {
        k_lu_panel<<<1, 512>>>(p);
        int Rt = NX - 32 * (p + 1);
        if (Rt > 0) {
            dim3 g(Rt / 32, Rt / 32);
            k_lu_trail<<<g, dim3(32, 32)>>>(p);
        }
    }
    k_logdet<<<1, 256>>>(logdet_out);

    // main fused batched GEMM
    dim3 grid(NX / BN, NT / BM, NSMP);
    k_gemm<<<grid, 256>>>(phi, W, out);
}

// round 16
// speedup vs baseline: 2.1282x; 2.1282x over previous
#include <cuda_runtime.h>
#include <cuda_bf16.h>
#include <math.h>
#include <stdint.h>

// Problem dims (fixed by the dataset)
#define NSMP 256
#define NT   512
#define NX   512

// ---------------------------------------------------------------------------
// Device scratch (no cudaMalloc allowed)
// ---------------------------------------------------------------------------
__device__ int   g_T0[NSMP];
__device__ float g_LU[NX * NX];
__device__ float g_logabsdet;

// ---------------------------------------------------------------------------
// Kernel 1: per-sample shift T0[i] = min(argmin_t |phi[i,t,0]|, argmin_t |phi[i,t,1]|)
// ---------------------------------------------------------------------------
__global__ void k_T0(const float* __restrict__ phi) {
    int i = blockIdx.x;
    int lane = threadIdx.x & 31;
    int x = threadIdx.x >> 5;  // 0 or 1
    const float* p = phi + (size_t)i * NT * NX + x;

    float best = 3.4e38f;
    int bidx = 0;
    for (int t = lane; t < NT; t += 32) {
        float v = fabsf(p[(size_t)t * NX]);
        if (v < best) { best = v; bidx = t; }
    }
    #pragma unroll
    for (int off = 16; off > 0; off >>= 1) {
        float ov = __shfl_down_sync(0xffffffffu, best, off);
        int   oi = __shfl_down_sync(0xffffffffu, bidx, off);
        if (ov < best || (ov == best && oi < bidx)) { best = ov; bidx = oi; }
    }
    __shared__ int s[2];
    if (lane == 0) s[x] = bidx;
    __syncthreads();
    if (threadIdx.x == 0) g_T0[i] = min(s[0], s[1]);
}

// ---------------------------------------------------------------------------
// Kernel 2: copy W -> LU scratch, zero the logdet accumulator
// ---------------------------------------------------------------------------
__global__ void k_copyW(const float* __restrict__ W) {
    int idx = blockIdx.x * blockDim.x + threadIdx.x;
    if (idx == 0) g_logabsdet = 0.0f;
    reinterpret_cast<float4*>(g_LU)[idx] = reinterpret_cast<const float4*>(W)[idx];
}

// ---------------------------------------------------------------------------
// Kernel 3: LU panel factorization (unpivoted), nb = 32, one block.
// ---------------------------------------------------------------------------
__global__ void __launch_bounds__(512) k_lu_panel(int p) {
    const int col0 = p * 32;
    const int R = NX - col0;
    const int t = threadIdx.x;
    const bool act = (t < R);

    __shared__ float srow[32];
    __shared__ float s_rinv;
    __shared__ float sL[32][33];

    float a[32];
    float* rowp = g_LU + (size_t)(col0 + t) * NX + col0;
    if (act) {
        #pragma unroll
        for (int q = 0; q < 8; q++) {
            float4 v = *reinterpret_cast<const float4*>(rowp + 4 * q);
            a[4 * q + 0] = v.x; a[4 * q + 1] = v.y;
            a[4 * q + 2] = v.z; a[4 * q + 3] = v.w;
        }
    }

    float lsum = 0.0f;
    #pragma unroll
    for (int j = 0; j < 32; j++) {
        if (t == j) {
            #pragma unroll
            for (int k = 0; k < 32; k++) srow[k] = a[k];
            s_rinv = 1.0f / a[j];
        }
        __syncthreads();
        if (t == 0) lsum += logf(fabsf(srow[j]));
        if (act && t > j) {
            float l = a[j] * s_rinv;
            a[j] = l;
            #pragma unroll
            for (int k = j + 1; k < 32; k++) a[k] -= l * srow[k];
        }
        __syncthreads();
    }

    if (act) {
        #pragma unroll
        for (int q = 0; q < 8; q++) {
            float4 v;
            v.x = a[4 * q + 0]; v.y = a[4 * q + 1];
            v.z = a[4 * q + 2]; v.w = a[4 * q + 3];
            *reinterpret_cast<float4*>(rowp + 4 * q) = v;
        }
    }
    if (t < 32) {
        #pragma unroll
        for (int k = 0; k < 32; k++) sL[t][k] = a[k];
    }
    if (t == 0) atomicAdd(&g_logabsdet, lsum);
    __syncthreads();

    const int nc = R - 32;
    if (t < nc) {
        const int c = col0 + 32 + t;
        float y[32];
        #pragma unroll
        for (int j = 0; j < 32; j++) y[j] = g_LU[(size_t)(col0 + j) * NX + c];
        #pragma unroll
        for (int k = 0; k < 32; k++) {
            #pragma unroll
            for (int j = k + 1; j < 32; j++) y[j] -= sL[j][k] * y[k];
        }
        #pragma unroll
        for (int j = 0; j < 32; j++) g_LU[(size_t)(col0 + j) * NX + c] = y[j];
    }
}

// ---------------------------------------------------------------------------
// Kernel 4: trailing Schur update  A22 -= L21 * U12  (K = 32)
// ---------------------------------------------------------------------------
__global__ void __launch_bounds__(1024) k_lu_trail(int p) {
    const int col0 = p * 32;
    const int r0 = col0 + 32 + blockIdx.y * 32;
    const int c0 = col0 + 32 + blockIdx.x * 32;
    const int ty = threadIdx.y, tx = threadIdx.x;

    __shared__ float sL[32][33];
    __shared__ float sU[32][33];
    sL[ty][tx] = g_LU[(size_t)(r0 + ty) * NX + col0 + tx];
    sU[ty][tx] = g_LU[(size_t)(col0 + ty) * NX + c0 + tx];
    __syncthreads();

    float acc = 0.0f;
    #pragma unroll
    for (int k = 0; k < 32; k++) acc += sL[ty][k] * sU[k][tx];
    g_LU[(size_t)(r0 + ty) * NX + c0 + tx] -= acc;
}

// ---------------------------------------------------------------------------
// Kernel 5: broadcast logDet
// ---------------------------------------------------------------------------
__global__ void k_logdet(float* __restrict__ dst) {
    int i = blockIdx.x * blockDim.x + threadIdx.x;
    if (i < NSMP) dst[i] = (float)NT * g_logabsdet;
}

// ---------------------------------------------------------------------------
// TF32 tensor-core GEMM with fused double-roll.
//   out[i, (t - T0)%NT, y] = sum_u phi[i,t,u] * W[(u + T0)%NX, y]
// CTA tile 128x128, 8 warps (4m x 2n), warp tile 32x64, BK=32.
// mma.sync.m16n8k8 tf32 (cvt.rna at fragment load -> unbiased rounding).
// cp.async 2-stage smem pipeline; B rows gathered at (k+T0)&511 (W native
// layout); C rows scattered at (t-T0)&511. fp32 accumulation.
// ---------------------------------------------------------------------------
#define ASTR 36                    // A smem row stride (floats): conflict-free frags, 16B-aligned
#define BSTR 132                   // B smem row stride (floats): 16B-aligned
#define A_BUF (128 * ASTR)         // 4608 floats per stage
#define B_BUF (32 * BSTR)          // 4224 floats per stage
#define SMEM_FLOATS (2 * A_BUF + 2 * B_BUF)  // 17664 floats = 70656 B

__device__ __forceinline__ uint32_t f2tf32(float f) {
    uint32_t u;
    asm("cvt.rna.tf32.f32 %0, %1;" : "=r"(u) : "f"(f));
    return u;
}
__device__ __forceinline__ void mma8(float* c, const uint32_t* a, uint32_t b0, uint32_t b1) {
    asm volatile(
        "mma.sync.aligned.m16n8k8.row.col.f32.tf32.tf32.f32 "
        "{%0,%1,%2,%3}, {%4,%5,%6,%7}, {%8,%9}, {%0,%1,%2,%3};"
        : "+f"(c[0]), "+f"(c[1]), "+f"(c[2]), "+f"(c[3])
        : "r"(a[0]), "r"(a[1]), "r"(a[2]), "r"(a[3]), "r"(b0), "r"(b1));
}
__device__ __forceinline__ void cpa16(uint32_t dst, const void* src) {
    asm volatile("cp.async.cg.shared.global [%0], [%1], 16;" :: "r"(dst), "l"(src));
}
__device__ __forceinline__ void cpcommit() {
    asm volatile("cp.async.commit_group;" ::: "memory");
}
template <int N>
__device__ __forceinline__ void cpwait() {
    asm volatile("cp.async.wait_group %0;" :: "n"(N) : "memory");
}

__global__ void __launch_bounds__(256) k_gemm_tc(const float* __restrict__ phi,
                                                const float* __restrict__ W,
                                                float* __restrict__ out) {
    extern __shared__ float sm[];
    const int i = blockIdx.z;
    const int T0 = g_T0[i];
    const int m0 = blockIdx.y * 128;
    const int n0 = blockIdx.x * 128;
    const float* A = phi + (size_t)i * NT * NX;
    float* C = out + (size_t)i * NT * NX;

    const int tid = threadIdx.x;
    const uint32_t smem_base = (uint32_t)__cvta_generic_to_shared(sm);

    const int wid = tid >> 5, lane = tid & 31;
    const int grp = lane >> 2, tig = lane & 3;
    const int wm = wid & 3, wn = wid >> 2;   // warp tile: rows wm*32, cols wn*64

    float acc[2][8][4];
    #pragma unroll
    for (int ii = 0; ii < 2; ii++)
        #pragma unroll
        for (int j = 0; j < 8; j++)
            #pragma unroll
            for (int r = 0; r < 4; r++) acc[ii][j][r] = 0.0f;

    // stage tile `it` into stage buffer `buf` via cp.async, then commit
    auto stage = [&](int it, int buf) {
        const int k0 = it * 32;
        #pragma unroll
        for (int q = 0; q < 4; q++) {            // A: 128x32 floats = 1024 f4
            int idx = tid + q * 256;
            int row = idx >> 3, c4 = idx & 7;
            const float* src = A + (size_t)(m0 + row) * NX + k0 + c4 * 4;
            uint32_t dst = smem_base +
                (uint32_t)(((buf ? A_BUF : 0) + row * ASTR + c4 * 4) * 4);
            cpa16(dst, src);
        }
        #pragma unroll
        for (int q = 0; q < 4; q++) {            // B: 32x128 floats = 1024 f4
            int idx = tid + q * 256;
            int kr = idx >> 5, c4 = idx & 31;
            int wrow = (k0 + kr + T0) & (NX - 1);
            const float* src = W + (size_t)wrow * NX + n0 + c4 * 4;
            uint32_t dst = smem_base +
                (uint32_t)((2 * A_BUF + (buf ? B_BUF : 0) + kr * BSTR + c4 * 4) * 4);
            cpa16(dst, src);
        }
        cpcommit();
    };

    stage(0, 0);

    for (int it = 0; it < 16; ++it) {
        const int buf = it & 1;
        if (it < 15) { stage(it + 1, buf ^ 1); cpwait<1>(); }
        else         { cpwait<0>(); }
        __syncthreads();

        const float* Ab = sm + (buf ? A_BUF : 0);
        const float* Bb = sm + 2 * A_BUF + (buf ? B_BUF : 0);

        #pragma unroll
        for (int kk = 0; kk < 32; kk += 8) {
            uint32_t a[2][4];
            #pragma unroll
            for (int ii = 0; ii < 2; ii++) {
                int r = wm * 32 + ii * 16 + grp;
                a[ii][0] = f2tf32(Ab[r * ASTR + kk + tig]);
                a[ii][1] = f2tf32(Ab[(r + 8) * ASTR + kk + tig]);
                a[ii][2] = f2tf32(Ab[r * ASTR + kk + tig + 4]);
                a[ii][3] = f2tf32(Ab[(r + 8) * ASTR + kk + tig + 4]);
            }
            #pragma unroll
            for (int j = 0; j < 8; j++) {
                int cb = wn * 64 + j * 8 + grp;
                uint32_t b0 = f2tf32(Bb[(kk + tig) * BSTR + cb]);
                uint32_t b1 = f2tf32(Bb[(kk + tig + 4) * BSTR + cb]);
                mma8(acc[0][j], a[0], b0, b1);
                mma8(acc[1][j], a[1], b0, b1);
            }
        }
        __syncthreads();   // protect buffer from next iteration's cp.async
    }

    // epilogue: row-rolled fp32 stores (c0,c1 at row grp; c2,c3 at row grp+8)
    #pragma unroll
    for (int ii = 0; ii < 2; ii++) {
        int rg = m0 + wm * 32 + ii * 16 + grp;
        int o0 = (rg - T0) & (NT - 1);
        int o1 = (rg + 8 - T0) & (NT - 1);
        #pragma unroll
        for (int j = 0; j < 8; j++) {
            int col = n0 + wn * 64 + j * 8 + tig * 2;
            *reinterpret_cast<float2*>(C + (size_t)o0 * NX + col) =
                make_float2(acc[ii][j][0], acc[ii][j][1]);
            *reinterpret_cast<float2*>(C + (size_t)o1 * NX + col) =
                make_float2(acc[ii][j][2], acc[ii][j][3]);
        }
    }
}

// ---------------------------------------------------------------------------
// Launch
// ---------------------------------------------------------------------------
extern "C" void kernel_launch(void* const* d_in, const int* in_sizes, int n_in,
                              void* d_out, int out_size) {
    const float* phi = (const float*)d_in[0];
    const float* W   = (const float*)d_in[1];
    if (n_in >= 2 && in_sizes[0] < in_sizes[1]) {
        phi = (const float*)d_in[1];
        W   = (const float*)d_in[0];
    }
    float* out = (float*)d_out;
    float* logdet_out = out + (size_t)(out_size - NSMP);

    // T0 shifts
    k_T0<<<NSMP, 64>>>(phi);

    // logdet branch: copy W, blocked LU, broadcast
    k_copyW<<<256, 256>>>(W);
    for (int p = 0; p < 16; p++) {
        k_lu_panel<<<1, 512>>>(p);
        int Rt = NX - 32 * (p + 1);
        if (Rt > 0) {
            dim3 g(Rt / 32, Rt / 32);
            k_lu_trail<<<g, dim3(32, 32)>>>(p);
        }
    }
    k_logdet<<<1, 256>>>(logdet_out);

    // main fused batched GEMM (TF32 tensor cores, dynamic smem > 48KB)
    cudaFuncSetAttribute(k_gemm_tc, cudaFuncAttributeMaxDynamicSharedMemorySize,
                         SMEM_FLOATS * 4);
    dim3 grid(4, 4, NSMP);
    k_gemm_tc<<<grid, 256, SMEM_FLOATS * 4>>>(phi, W, out);
}